// round 4
// baseline (speedup 1.0000x reference)
#include <cuda_runtime.h>
#include <cuda_bf16.h>

#define NA 100000
#define NB 50000
#define DIM 128
#define EE 1000000

// ---- static device scratch ----
// Aggregates (post-gather, pre-GEMM):
//   g_agg_a [NA, 256]: cols 0..127  = sum_ba x_b[s]*rsqrt(ds_ba[s]) * rsqrt(dt_ba[d])
//                      cols 128..255= sum_aa x_a[s]*rsqrt(ds_aa[s]) * rsqrt(dt_aa[d])
//   g_agg_b [NB, 128]: sum_ab x_a[s]*rsqrt(ds_ab[s]) * rsqrt(dt_ab[d])
__device__ float g_agg_a[(size_t)NA * 256];
__device__ float g_agg_b[(size_t)NB * DIM];

__device__ int g_deg_s_ab[NA];
__device__ int g_deg_t_ab[NB];
__device__ int g_deg_s_ba[NB];
__device__ int g_deg_t_ba[NA];
__device__ int g_deg_s_aa[NA];
__device__ int g_deg_t_aa[NA];

// CSR-by-dst
__device__ int g_rs_ab[NB];
__device__ int g_rs_ba[NA];
__device__ int g_rs_aa[NA];
__device__ int g_cur_ab[NB];
__device__ int g_cur_ba[NA];
__device__ int g_cur_aa[NA];
__device__ int g_csr_ab[EE];
__device__ int g_csr_ba[EE];
__device__ int g_csr_aa[EE];

// ---------------------------------------------------------------------
__global__ void zero_kernel() {
    int i = blockIdx.x * blockDim.x + threadIdx.x;
    int stride = gridDim.x * blockDim.x;
    for (int j = i; j < NA; j += stride) {
        g_deg_s_ab[j] = 0;
        g_deg_t_ba[j] = 0;
        g_deg_s_aa[j] = 0;
        g_deg_t_aa[j] = 0;
    }
    for (int j = i; j < NB; j += stride) {
        g_deg_t_ab[j] = 0;
        g_deg_s_ba[j] = 0;
    }
}

// ---------------------------------------------------------------------
// dst-degree histograms only (src degrees handled in fill_kernel)
// ---------------------------------------------------------------------
__global__ void degree_kernel(const int* __restrict__ dst_ab,
                              const int* __restrict__ dst_ba,
                              const int* __restrict__ dst_aa) {
    int i = blockIdx.x * blockDim.x + threadIdx.x;
    if (i >= EE) return;
    atomicAdd(&g_deg_t_ab[dst_ab[i]], 1);
    atomicAdd(&g_deg_t_ba[dst_ba[i]], 1);
    atomicAdd(&g_deg_t_aa[dst_aa[i]], 1);
}

// ---------------------------------------------------------------------
// Exclusive scan of the 3 dst-degree arrays (one block per array).
// ---------------------------------------------------------------------
__global__ __launch_bounds__(1024) void scan3_kernel() {
    const int* deg;
    int n;
    int* rs;
    int* cur;
    if (blockIdx.x == 0)      { deg = g_deg_t_ab; n = NB; rs = g_rs_ab; cur = g_cur_ab; }
    else if (blockIdx.x == 1) { deg = g_deg_t_ba; n = NA; rs = g_rs_ba; cur = g_cur_ba; }
    else                      { deg = g_deg_t_aa; n = NA; rs = g_rs_aa; cur = g_cur_aa; }

    const int t = threadIdx.x;
    const int chunk = (n + 1023) >> 10;
    const int lo = t * chunk;
    const int hi = min(lo + chunk, n);

    int s = 0;
    for (int i = lo; i < hi; i++) s += deg[i];

    __shared__ int sm[1024];
    sm[t] = s;
    __syncthreads();
    for (int off = 1; off < 1024; off <<= 1) {
        int v = (t >= off) ? sm[t - off] : 0;
        __syncthreads();
        sm[t] += v;
        __syncthreads();
    }
    int base = (t > 0) ? sm[t - 1] : 0;
    for (int i = lo; i < hi; i++) {
        rs[i] = base;
        cur[i] = base;
        base += deg[i];
    }
}

// ---------------------------------------------------------------------
// Fill CSR buckets + src-degree histograms
// ---------------------------------------------------------------------
__global__ void fill_kernel(const int* __restrict__ src_ab, const int* __restrict__ dst_ab,
                            const int* __restrict__ src_ba, const int* __restrict__ dst_ba,
                            const int* __restrict__ src_aa, const int* __restrict__ dst_aa) {
    int i = blockIdx.x * blockDim.x + threadIdx.x;
    if (i >= EE) return;
    int s, p;
    s = src_ab[i];
    atomicAdd(&g_deg_s_ab[s], 1);
    p = atomicAdd(&g_cur_ab[dst_ab[i]], 1); g_csr_ab[p] = s;
    s = src_ba[i];
    atomicAdd(&g_deg_s_ba[s], 1);
    p = atomicAdd(&g_cur_ba[dst_ba[i]], 1); g_csr_ba[p] = s;
    s = src_aa[i];
    atomicAdd(&g_deg_s_aa[s], 1);
    p = atomicAdd(&g_cur_aa[dst_aa[i]], 1); g_csr_aa[p] = s;
}

// ---------------------------------------------------------------------
// Warp-per-node gather of raw x rows, scaled per edge by rsqrt(deg_s[src]).
// ---------------------------------------------------------------------
__device__ __forceinline__ float4 gather_accum(const int* __restrict__ csr,
                                               const int* __restrict__ deg_s,
                                               int start, int cnt,
                                               const float* __restrict__ x, int lane) {
    float4 acc = make_float4(0.f, 0.f, 0.f, 0.f);
    int j = 0;
    while (j < cnt) {
        int m = min(32, cnt - j);
        int idx = 0;
        float inv = 0.f;
        if (lane < m) {
            idx = csr[start + j + lane];
            inv = rsqrtf((float)deg_s[idx]);
        }
#pragma unroll 4
        for (int k = 0; k < m; k++) {
            int s = __shfl_sync(0xffffffffu, idx, k);
            float iv = __shfl_sync(0xffffffffu, inv, k);
            float4 v = *reinterpret_cast<const float4*>(&x[(size_t)s * DIM + lane * 4]);
            acc.x += v.x * iv; acc.y += v.y * iv; acc.z += v.z * iv; acc.w += v.w * iv;
        }
        j += m;
    }
    return acc;
}

// One warp per output node; writes the pre-GEMM aggregate (deg_t scaling applied).
__global__ __launch_bounds__(256) void gather_kernel(const float* __restrict__ x_a,
                                                     const float* __restrict__ x_b) {
    long long gw = (long long)blockIdx.x * (blockDim.x >> 5) + (threadIdx.x >> 5);
    int lane = threadIdx.x & 31;
    if (gw >= (long long)(NA + NB)) return;

    if (gw < NA) {
        int d = (int)gw;
        int c_ba = g_deg_t_ba[d];
        int c_aa = g_deg_t_aa[d];
        float4 s_ba = gather_accum(g_csr_ba, g_deg_s_ba, g_rs_ba[d], c_ba, x_b, lane);
        float4 s_aa = gather_accum(g_csr_aa, g_deg_s_aa, g_rs_aa[d], c_aa, x_a, lane);
        float rb = (c_ba > 0) ? rsqrtf((float)c_ba) : 0.f;
        float ra = (c_aa > 0) ? rsqrtf((float)c_aa) : 0.f;
        float4 vb = make_float4(s_ba.x * rb, s_ba.y * rb, s_ba.z * rb, s_ba.w * rb);
        float4 va = make_float4(s_aa.x * ra, s_aa.y * ra, s_aa.z * ra, s_aa.w * ra);
        *reinterpret_cast<float4*>(&g_agg_a[(size_t)d * 256 + lane * 4]) = vb;
        *reinterpret_cast<float4*>(&g_agg_a[(size_t)d * 256 + 128 + lane * 4]) = va;
    } else {
        int d = (int)(gw - NA);
        int c_ab = g_deg_t_ab[d];
        float4 s_ab = gather_accum(g_csr_ab, g_deg_s_ab, g_rs_ab[d], c_ab, x_a, lane);
        float r = (c_ab > 0) ? rsqrtf((float)c_ab) : 0.f;
        float4 v = make_float4(s_ab.x * r, s_ab.y * r, s_ab.z * r, s_ab.w * r);
        *reinterpret_cast<float4*>(&g_agg_b[(size_t)d * DIM + lane * 4]) = v;
    }
}

// ---------------------------------------------------------------------
// SGEMM with fused epilogue: OUT = relu( (A[:, :K] @ Wcat) * scale )
// Wcat rows 0..127 from W0, 128..255 from W1 (if K=256).
// BM=64, BN=128, BK=32, 256 threads, 8x4 micro-tile.
// ---------------------------------------------------------------------
__global__ __launch_bounds__(256) void gemm_epi_kernel(const float* __restrict__ A, int lda,
                                                       const float* __restrict__ W0,
                                                       const float* __restrict__ W1,
                                                       int K,
                                                       float* __restrict__ OUT,
                                                       int nrows, float scale) {
    __shared__ float As[32][65];
    __shared__ float Bs[32][128];

    const int t = threadIdx.x;
    const int tn = t & 31;
    const int tm = t >> 5;
    const int row0 = blockIdx.x * 64;

    float acc[8][4];
#pragma unroll
    for (int i = 0; i < 8; i++)
#pragma unroll
        for (int j = 0; j < 4; j++) acc[i][j] = 0.f;

    for (int k0 = 0; k0 < K; k0 += 32) {
#pragma unroll
        for (int l = 0; l < 2; l++) {
            int i = t + l * 256;
            int r = i >> 3;
            int kq = (i & 7) * 4;
            float4 v = make_float4(0.f, 0.f, 0.f, 0.f);
            if (row0 + r < nrows)
                v = *reinterpret_cast<const float4*>(&A[(size_t)(row0 + r) * lda + k0 + kq]);
            As[kq + 0][r] = v.x;
            As[kq + 1][r] = v.y;
            As[kq + 2][r] = v.z;
            As[kq + 3][r] = v.w;
        }
        const float* Wp = (k0 < 128) ? (W0 + (size_t)k0 * DIM)
                                     : (W1 + (size_t)(k0 - 128) * DIM);
#pragma unroll
        for (int l = 0; l < 4; l++) {
            int i = t + l * 256;
            reinterpret_cast<float4*>(&Bs[0][0])[i] =
                reinterpret_cast<const float4*>(Wp)[i];
        }
        __syncthreads();

#pragma unroll
        for (int k = 0; k < 32; k++) {
            float a[8], b[4];
#pragma unroll
            for (int i = 0; i < 8; i++) a[i] = As[k][tm * 8 + i];
            float4 bv = *reinterpret_cast<const float4*>(&Bs[k][tn * 4]);
            b[0] = bv.x; b[1] = bv.y; b[2] = bv.z; b[3] = bv.w;
#pragma unroll
            for (int i = 0; i < 8; i++)
#pragma unroll
                for (int j = 0; j < 4; j++) acc[i][j] += a[i] * b[j];
        }
        __syncthreads();
    }

#pragma unroll
    for (int i = 0; i < 8; i++) {
        int r = row0 + tm * 8 + i;
        if (r < nrows) {
            float4 v;
            v.x = fmaxf(acc[i][0] * scale, 0.f);
            v.y = fmaxf(acc[i][1] * scale, 0.f);
            v.z = fmaxf(acc[i][2] * scale, 0.f);
            v.w = fmaxf(acc[i][3] * scale, 0.f);
            *reinterpret_cast<float4*>(&OUT[(size_t)r * DIM + tn * 4]) = v;
        }
    }
}

// ---------------------------------------------------------------------
extern "C" void kernel_launch(void* const* d_in, const int* in_sizes, int n_in,
                              void* d_out, int out_size) {
    const float* x_a  = (const float*)d_in[0];
    const float* x_b  = (const float*)d_in[1];
    const float* W_ab = (const float*)d_in[2];
    const float* W_ba = (const float*)d_in[3];
    const float* W_aa = (const float*)d_in[4];
    const int* src_ab = (const int*)d_in[5];
    const int* dst_ab = (const int*)d_in[6];
    const int* src_ba = (const int*)d_in[7];
    const int* dst_ba = (const int*)d_in[8];
    const int* src_aa = (const int*)d_in[9];
    const int* dst_aa = (const int*)d_in[10];

    float* out   = (float*)d_out;
    float* out_a = out;                       // [NA,128]
    float* out_b = out + (size_t)NA * DIM;    // [NB,128]

    float *agg_a, *agg_b;
    cudaGetSymbolAddress((void**)&agg_a, g_agg_a);
    cudaGetSymbolAddress((void**)&agg_b, g_agg_b);

    zero_kernel<<<512, 256>>>();

    degree_kernel<<<(EE + 255) / 256, 256>>>(dst_ab, dst_ba, dst_aa);

    scan3_kernel<<<3, 1024>>>();

    fill_kernel<<<(EE + 255) / 256, 256>>>(src_ab, dst_ab, src_ba, dst_ba, src_aa, dst_aa);

    // aggregate raw x rows per destination node (one warp per node)
    {
        long long nwarps = NA + NB;
        int blocks = (int)((nwarps + 7) / 8);
        gather_kernel<<<blocks, 256>>>(x_a, x_b);
    }

    // out_a = relu( (agg_ba @ W_ba + agg_aa @ W_aa) * 0.5 )   (K=256 concat GEMM)
    gemm_epi_kernel<<<(NA + 63) / 64, 256>>>(agg_a, 256, W_ba, W_aa, 256, out_a, NA, 0.5f);
    // out_b = relu( agg_ab @ W_ab )
    gemm_epi_kernel<<<(NB + 63) / 64, 256>>>(agg_b, 128, W_ab, W_ab, 128, out_b, NB, 1.0f);
}

// round 5
// speedup vs baseline: 1.0353x; 1.0353x over previous
#include <cuda_runtime.h>
#include <cuda_bf16.h>

#define NA 100000
#define NB 50000
#define DIM 128
#define EE 1000000

// ---- static device scratch ----
__device__ float g_h_ab[(size_t)NA * DIM];   // (x_a @ W_ab) * rsqrt(deg_s_ab)  -> out_b
__device__ float g_h_ba[(size_t)NB * DIM];   // (x_b @ W_ba) * rsqrt(deg_s_ba)  -> out_a
__device__ float g_h_aa[(size_t)NA * DIM];   // (x_a @ W_aa) * rsqrt(deg_s_aa)  -> out_a

__device__ int g_deg_s_ab[NA];
__device__ int g_deg_t_ab[NB];
__device__ int g_deg_s_ba[NB];
__device__ int g_deg_t_ba[NA];
__device__ int g_deg_s_aa[NA];
__device__ int g_deg_t_aa[NA];

// CSR-by-dst
__device__ int g_rs_ab[NB];
__device__ int g_rs_ba[NA];
__device__ int g_rs_aa[NA];
__device__ int g_cur_ab[NB];
__device__ int g_cur_ba[NA];
__device__ int g_cur_aa[NA];
__device__ int g_csr_ab[EE];
__device__ int g_csr_ba[EE];
__device__ int g_csr_aa[EE];

// ---------------------------------------------------------------------
__global__ void zero_kernel() {
    int i = blockIdx.x * blockDim.x + threadIdx.x;
    int stride = gridDim.x * blockDim.x;
    for (int j = i; j < NA; j += stride) {
        g_deg_s_ab[j] = 0;
        g_deg_t_ba[j] = 0;
        g_deg_s_aa[j] = 0;
        g_deg_t_aa[j] = 0;
    }
    for (int j = i; j < NB; j += stride) {
        g_deg_t_ab[j] = 0;
        g_deg_s_ba[j] = 0;
    }
}

// ---------------------------------------------------------------------
// Degree histograms for all 3 edge types (src + dst)
// ---------------------------------------------------------------------
__global__ void degree_kernel(const int* __restrict__ src_ab, const int* __restrict__ dst_ab,
                              const int* __restrict__ src_ba, const int* __restrict__ dst_ba,
                              const int* __restrict__ src_aa, const int* __restrict__ dst_aa) {
    int i = blockIdx.x * blockDim.x + threadIdx.x;
    if (i >= EE) return;
    atomicAdd(&g_deg_s_ab[src_ab[i]], 1);
    atomicAdd(&g_deg_t_ab[dst_ab[i]], 1);
    atomicAdd(&g_deg_s_ba[src_ba[i]], 1);
    atomicAdd(&g_deg_t_ba[dst_ba[i]], 1);
    atomicAdd(&g_deg_s_aa[src_aa[i]], 1);
    atomicAdd(&g_deg_t_aa[dst_aa[i]], 1);
}

// ---------------------------------------------------------------------
// Exclusive scan of the 3 dst-degree arrays (one block per array).
// ---------------------------------------------------------------------
__global__ __launch_bounds__(1024) void scan3_kernel() {
    const int* deg;
    int n;
    int* rs;
    int* cur;
    if (blockIdx.x == 0)      { deg = g_deg_t_ab; n = NB; rs = g_rs_ab; cur = g_cur_ab; }
    else if (blockIdx.x == 1) { deg = g_deg_t_ba; n = NA; rs = g_rs_ba; cur = g_cur_ba; }
    else                      { deg = g_deg_t_aa; n = NA; rs = g_rs_aa; cur = g_cur_aa; }

    const int t = threadIdx.x;
    const int chunk = (n + 1023) >> 10;
    const int lo = t * chunk;
    const int hi = min(lo + chunk, n);

    int s = 0;
    for (int i = lo; i < hi; i++) s += deg[i];

    __shared__ int sm[1024];
    sm[t] = s;
    __syncthreads();
    for (int off = 1; off < 1024; off <<= 1) {
        int v = (t >= off) ? sm[t - off] : 0;
        __syncthreads();
        sm[t] += v;
        __syncthreads();
    }
    int base = (t > 0) ? sm[t - 1] : 0;
    for (int i = lo; i < hi; i++) {
        rs[i] = base;
        cur[i] = base;
        base += deg[i];
    }
}

// ---------------------------------------------------------------------
// Fill CSR buckets (order within a bucket irrelevant for a sum)
// ---------------------------------------------------------------------
__global__ void fill_kernel(const int* __restrict__ src_ab, const int* __restrict__ dst_ab,
                            const int* __restrict__ src_ba, const int* __restrict__ dst_ba,
                            const int* __restrict__ src_aa, const int* __restrict__ dst_aa) {
    int i = blockIdx.x * blockDim.x + threadIdx.x;
    if (i >= EE) return;
    int p;
    p = atomicAdd(&g_cur_ab[dst_ab[i]], 1); g_csr_ab[p] = src_ab[i];
    p = atomicAdd(&g_cur_ba[dst_ba[i]], 1); g_csr_ba[p] = src_ba[i];
    p = atomicAdd(&g_cur_aa[dst_aa[i]], 1); g_csr_aa[p] = src_aa[i];
}

// ---------------------------------------------------------------------
// SGEMM with packed f32x2 FMA: H = (X @ W) * rsqrt(deg_s[row])
// BM=64, BN=128, BK=32, 256 threads. Per-thread tile: 8 rows x 4 cols,
// computed as 4 row-PAIRS x 4 cols with fma.rn.f32x2 (2 fp32 FMA / issue).
// ---------------------------------------------------------------------
__global__ __launch_bounds__(256) void gemm128_kernel(const float* __restrict__ X,
                                                      const float* __restrict__ W,
                                                      float* __restrict__ H,
                                                      const int* __restrict__ degs,
                                                      int nrows) {
    __shared__ float As[32][66];    // [k][m], stride 66 (even -> 8B-aligned b64 loads)
    __shared__ float Bs[32][128];   // [k][n]

    const int t = threadIdx.x;
    const int tn = t & 31;   // col group (4 cols)
    const int tm = t >> 5;   // row group (8 rows)
    const int row0 = blockIdx.x * 64;

    unsigned long long acc2[4][4];  // [row-pair][col]: (row 2ii, row 2ii+1)
#pragma unroll
    for (int i = 0; i < 4; i++)
#pragma unroll
        for (int j = 0; j < 4; j++) acc2[i][j] = 0ull;

    const unsigned aBase = (unsigned)__cvta_generic_to_shared(&As[0][tm * 8]);

    for (int k0 = 0; k0 < 128; k0 += 32) {
        // A tile: 64 rows x 32 k, float4 along k
#pragma unroll
        for (int l = 0; l < 2; l++) {
            int i = t + l * 256;         // 0..511
            int r = i >> 3;              // 0..63
            int kq = (i & 7) * 4;        // 0,4,...,28
            float4 v = make_float4(0.f, 0.f, 0.f, 0.f);
            if (row0 + r < nrows)
                v = *reinterpret_cast<const float4*>(&X[(size_t)(row0 + r) * DIM + k0 + kq]);
            As[kq + 0][r] = v.x;
            As[kq + 1][r] = v.y;
            As[kq + 2][r] = v.z;
            As[kq + 3][r] = v.w;
        }
        // B tile: 32 k x 128 n
#pragma unroll
        for (int l = 0; l < 4; l++) {
            int i = t + l * 256;
            reinterpret_cast<float4*>(&Bs[0][0])[i] =
                reinterpret_cast<const float4*>(&W[(size_t)k0 * DIM])[i];
        }
        __syncthreads();

        unsigned aAddr = aBase;
#pragma unroll
        for (int k = 0; k < 32; k++) {
            unsigned long long a2[4];
#pragma unroll
            for (int ii = 0; ii < 4; ii++)
                asm volatile("ld.shared.b64 %0, [%1];"
                             : "=l"(a2[ii]) : "r"(aAddr + ii * 8));
            float4 bv = *reinterpret_cast<const float4*>(&Bs[k][tn * 4]);
            unsigned long long bd[4];
            asm("mov.b64 %0, {%1, %1};" : "=l"(bd[0]) : "f"(bv.x));
            asm("mov.b64 %0, {%1, %1};" : "=l"(bd[1]) : "f"(bv.y));
            asm("mov.b64 %0, {%1, %1};" : "=l"(bd[2]) : "f"(bv.z));
            asm("mov.b64 %0, {%1, %1};" : "=l"(bd[3]) : "f"(bv.w));
#pragma unroll
            for (int ii = 0; ii < 4; ii++)
#pragma unroll
                for (int j = 0; j < 4; j++)
                    asm("fma.rn.f32x2 %0, %1, %2, %0;"
                        : "+l"(acc2[ii][j]) : "l"(a2[ii]), "l"(bd[j]));
            aAddr += 66 * 4;
        }
        __syncthreads();
    }

#pragma unroll
    for (int ii = 0; ii < 4; ii++) {
        float lo[4], hi[4];
#pragma unroll
        for (int j = 0; j < 4; j++)
            asm("mov.b64 {%0, %1}, %2;" : "=f"(lo[j]), "=f"(hi[j]) : "l"(acc2[ii][j]));
        int r0 = row0 + tm * 8 + 2 * ii;
        if (r0 < nrows) {
            int dg = degs[r0];
            float inv = rsqrtf((float)(dg > 0 ? dg : 1));
            float4 v = make_float4(lo[0] * inv, lo[1] * inv, lo[2] * inv, lo[3] * inv);
            *reinterpret_cast<float4*>(&H[(size_t)r0 * DIM + tn * 4]) = v;
        }
        int r1 = r0 + 1;
        if (r1 < nrows) {
            int dg = degs[r1];
            float inv = rsqrtf((float)(dg > 0 ? dg : 1));
            float4 v = make_float4(hi[0] * inv, hi[1] * inv, hi[2] * inv, hi[3] * inv);
            *reinterpret_cast<float4*>(&H[(size_t)r1 * DIM + tn * 4]) = v;
        }
    }
}

// ---------------------------------------------------------------------
// Warp-per-node gather over a 64-column slice (float2 per lane).
// Two sequential launches (colOff = 0, 64) keep the h working set at
// 64 MB per pass -> L2-resident random reads.
// ---------------------------------------------------------------------
__device__ __forceinline__ float2 gather_accum2(const int* __restrict__ csr,
                                                int start, int cnt,
                                                const float* __restrict__ h, int c) {
    float2 acc = make_float2(0.f, 0.f);
    int lane = threadIdx.x & 31;
    int j = 0;
    while (j + 32 <= cnt) {
        int idx = csr[start + j + lane];
#pragma unroll 8
        for (int k = 0; k < 32; k++) {
            int s = __shfl_sync(0xffffffffu, idx, k);
            float2 v = *reinterpret_cast<const float2*>(&h[(size_t)s * DIM + c]);
            acc.x += v.x; acc.y += v.y;
        }
        j += 32;
    }
    int rem = cnt - j;
    if (rem > 0) {
        int idx = (lane < rem) ? csr[start + j + lane] : 0;
#pragma unroll 4
        for (int k = 0; k < rem; k++) {
            int s = __shfl_sync(0xffffffffu, idx, k);
            float2 v = *reinterpret_cast<const float2*>(&h[(size_t)s * DIM + c]);
            acc.x += v.x; acc.y += v.y;
        }
    }
    return acc;
}

__global__ __launch_bounds__(256) void gather_kernel(float* __restrict__ out_a,
                                                     float* __restrict__ out_b,
                                                     int colOff) {
    long long gw = (long long)blockIdx.x * (blockDim.x >> 5) + (threadIdx.x >> 5);
    int lane = threadIdx.x & 31;
    if (gw >= (long long)(NA + NB)) return;
    int c = colOff + lane * 2;

    if (gw < NA) {
        int d = (int)gw;
        int c_ba = g_deg_t_ba[d];
        int c_aa = g_deg_t_aa[d];
        float2 s_ba = gather_accum2(g_csr_ba, g_rs_ba[d], c_ba, g_h_ba, c);
        float2 s_aa = gather_accum2(g_csr_aa, g_rs_aa[d], c_aa, g_h_aa, c);
        float rb = (c_ba > 0) ? rsqrtf((float)c_ba) * 0.5f : 0.f;
        float ra = (c_aa > 0) ? rsqrtf((float)c_aa) * 0.5f : 0.f;
        float2 v;
        v.x = fmaxf(s_ba.x * rb + s_aa.x * ra, 0.f);
        v.y = fmaxf(s_ba.y * rb + s_aa.y * ra, 0.f);
        *reinterpret_cast<float2*>(&out_a[(size_t)d * DIM + c]) = v;
    } else {
        int d = (int)(gw - NA);
        int c_ab = g_deg_t_ab[d];
        float2 s_ab = gather_accum2(g_csr_ab, g_rs_ab[d], c_ab, g_h_ab, c);
        float r = (c_ab > 0) ? rsqrtf((float)c_ab) : 0.f;
        float2 v;
        v.x = fmaxf(s_ab.x * r, 0.f);
        v.y = fmaxf(s_ab.y * r, 0.f);
        *reinterpret_cast<float2*>(&out_b[(size_t)d * DIM + c]) = v;
    }
}

// ---------------------------------------------------------------------
extern "C" void kernel_launch(void* const* d_in, const int* in_sizes, int n_in,
                              void* d_out, int out_size) {
    const float* x_a  = (const float*)d_in[0];
    const float* x_b  = (const float*)d_in[1];
    const float* W_ab = (const float*)d_in[2];
    const float* W_ba = (const float*)d_in[3];
    const float* W_aa = (const float*)d_in[4];
    const int* src_ab = (const int*)d_in[5];
    const int* dst_ab = (const int*)d_in[6];
    const int* src_ba = (const int*)d_in[7];
    const int* dst_ba = (const int*)d_in[8];
    const int* src_aa = (const int*)d_in[9];
    const int* dst_aa = (const int*)d_in[10];

    float* out   = (float*)d_out;
    float* out_a = out;                       // [NA,128]
    float* out_b = out + (size_t)NA * DIM;    // [NB,128]

    float *h_ab, *h_ba, *h_aa;
    cudaGetSymbolAddress((void**)&h_ab, g_h_ab);
    cudaGetSymbolAddress((void**)&h_ba, g_h_ba);
    cudaGetSymbolAddress((void**)&h_aa, g_h_aa);

    int *d_s_ab, *d_s_ba, *d_s_aa;
    cudaGetSymbolAddress((void**)&d_s_ab, g_deg_s_ab);
    cudaGetSymbolAddress((void**)&d_s_ba, g_deg_s_ba);
    cudaGetSymbolAddress((void**)&d_s_aa, g_deg_s_aa);

    zero_kernel<<<512, 256>>>();

    degree_kernel<<<(EE + 255) / 256, 256>>>(src_ab, dst_ab, src_ba, dst_ba, src_aa, dst_aa);

    scan3_kernel<<<3, 1024>>>();

    fill_kernel<<<(EE + 255) / 256, 256>>>(src_ab, dst_ab, src_ba, dst_ba, src_aa, dst_aa);

    gemm128_kernel<<<(NA + 63) / 64, 256>>>(x_a, W_ab, h_ab, d_s_ab, NA);
    gemm128_kernel<<<(NB + 63) / 64, 256>>>(x_b, W_ba, h_ba, d_s_ba, NB);
    gemm128_kernel<<<(NA + 63) / 64, 256>>>(x_a, W_aa, h_aa, d_s_aa, NA);

    // one warp per output node, two sequential column-slice passes
    long long nwarps = NA + NB;
    int blocks = (int)((nwarps + 7) / 8);
    gather_kernel<<<blocks, 256>>>(out_a, out_b, 0);
    gather_kernel<<<blocks, 256>>>(out_a, out_b, 64);
}

// round 6
// speedup vs baseline: 1.0951x; 1.0578x over previous
#include <cuda_runtime.h>
#include <cuda_bf16.h>

#define NA 100000
#define NB 50000
#define DIM 128
#define EE 1000000

// ---- static device scratch ----
__device__ float g_h_ab[(size_t)NA * DIM];   // (x_a @ W_ab) * rsqrt(deg_s_ab)  -> out_b
__device__ float g_h_ba[(size_t)NB * DIM];   // (x_b @ W_ba) * rsqrt(deg_s_ba)  -> out_a
__device__ float g_h_aa[(size_t)NA * DIM];   // (x_a @ W_aa) * rsqrt(deg_s_aa)  -> out_a

__device__ int g_deg_s_ab[NA];
__device__ int g_deg_t_ab[NB];
__device__ int g_deg_s_ba[NB];
__device__ int g_deg_t_ba[NA];
__device__ int g_deg_s_aa[NA];
__device__ int g_deg_t_aa[NA];

// CSR-by-dst
__device__ int g_rs_ab[NB];
__device__ int g_rs_ba[NA];
__device__ int g_rs_aa[NA];
__device__ int g_cur_ab[NB];
__device__ int g_cur_ba[NA];
__device__ int g_cur_aa[NA];
__device__ int g_csr_ab[EE];
__device__ int g_csr_ba[EE];
__device__ int g_csr_aa[EE];

// ---------------------------------------------------------------------
__global__ void zero_kernel() {
    int i = blockIdx.x * blockDim.x + threadIdx.x;
    int stride = gridDim.x * blockDim.x;
    for (int j = i; j < NA; j += stride) {
        g_deg_s_ab[j] = 0;
        g_deg_t_ba[j] = 0;
        g_deg_s_aa[j] = 0;
        g_deg_t_aa[j] = 0;
    }
    for (int j = i; j < NB; j += stride) {
        g_deg_t_ab[j] = 0;
        g_deg_s_ba[j] = 0;
    }
}

// ---------------------------------------------------------------------
// Degree histograms for all 3 edge types (src + dst)
// ---------------------------------------------------------------------
__global__ void degree_kernel(const int* __restrict__ src_ab, const int* __restrict__ dst_ab,
                              const int* __restrict__ src_ba, const int* __restrict__ dst_ba,
                              const int* __restrict__ src_aa, const int* __restrict__ dst_aa) {
    int i = blockIdx.x * blockDim.x + threadIdx.x;
    if (i >= EE) return;
    atomicAdd(&g_deg_s_ab[src_ab[i]], 1);
    atomicAdd(&g_deg_t_ab[dst_ab[i]], 1);
    atomicAdd(&g_deg_s_ba[src_ba[i]], 1);
    atomicAdd(&g_deg_t_ba[dst_ba[i]], 1);
    atomicAdd(&g_deg_s_aa[src_aa[i]], 1);
    atomicAdd(&g_deg_t_aa[dst_aa[i]], 1);
}

// ---------------------------------------------------------------------
// Exclusive scan of the 3 dst-degree arrays (one block per array).
// ---------------------------------------------------------------------
__global__ __launch_bounds__(1024) void scan3_kernel() {
    const int* deg;
    int n;
    int* rs;
    int* cur;
    if (blockIdx.x == 0)      { deg = g_deg_t_ab; n = NB; rs = g_rs_ab; cur = g_cur_ab; }
    else if (blockIdx.x == 1) { deg = g_deg_t_ba; n = NA; rs = g_rs_ba; cur = g_cur_ba; }
    else                      { deg = g_deg_t_aa; n = NA; rs = g_rs_aa; cur = g_cur_aa; }

    const int t = threadIdx.x;
    const int chunk = (n + 1023) >> 10;
    const int lo = t * chunk;
    const int hi = min(lo + chunk, n);

    int s = 0;
    for (int i = lo; i < hi; i++) s += deg[i];

    __shared__ int sm[1024];
    sm[t] = s;
    __syncthreads();
    for (int off = 1; off < 1024; off <<= 1) {
        int v = (t >= off) ? sm[t - off] : 0;
        __syncthreads();
        sm[t] += v;
        __syncthreads();
    }
    int base = (t > 0) ? sm[t - 1] : 0;
    for (int i = lo; i < hi; i++) {
        rs[i] = base;
        cur[i] = base;
        base += deg[i];
    }
}

// ---------------------------------------------------------------------
// Fill CSR buckets (order within a bucket irrelevant for a sum)
// ---------------------------------------------------------------------
__global__ void fill_kernel(const int* __restrict__ src_ab, const int* __restrict__ dst_ab,
                            const int* __restrict__ src_ba, const int* __restrict__ dst_ba,
                            const int* __restrict__ src_aa, const int* __restrict__ dst_aa) {
    int i = blockIdx.x * blockDim.x + threadIdx.x;
    if (i >= EE) return;
    int p;
    p = atomicAdd(&g_cur_ab[dst_ab[i]], 1); g_csr_ab[p] = src_ab[i];
    p = atomicAdd(&g_cur_ba[dst_ba[i]], 1); g_csr_ba[p] = src_ba[i];
    p = atomicAdd(&g_cur_aa[dst_aa[i]], 1); g_csr_aa[p] = src_aa[i];
}

// ---------------------------------------------------------------------
// SGEMM: H = (X @ W) * rsqrt(deg_s[row])  (R3 known-good version)
// BM=64, BN=128, BK=32, 256 threads, 8x4 micro-tile.
// ---------------------------------------------------------------------
__global__ __launch_bounds__(256) void gemm128_kernel(const float* __restrict__ X,
                                                      const float* __restrict__ W,
                                                      float* __restrict__ H,
                                                      const int* __restrict__ degs,
                                                      int nrows) {
    __shared__ float As[32][65];
    __shared__ float Bs[32][128];

    const int t = threadIdx.x;
    const int tn = t & 31;
    const int tm = t >> 5;
    const int row0 = blockIdx.x * 64;

    float acc[8][4];
#pragma unroll
    for (int i = 0; i < 8; i++)
#pragma unroll
        for (int j = 0; j < 4; j++) acc[i][j] = 0.f;

    for (int k0 = 0; k0 < 128; k0 += 32) {
#pragma unroll
        for (int l = 0; l < 2; l++) {
            int i = t + l * 256;
            int r = i >> 3;
            int kq = (i & 7) * 4;
            float4 v = make_float4(0.f, 0.f, 0.f, 0.f);
            if (row0 + r < nrows)
                v = *reinterpret_cast<const float4*>(&X[(size_t)(row0 + r) * DIM + k0 + kq]);
            As[kq + 0][r] = v.x;
            As[kq + 1][r] = v.y;
            As[kq + 2][r] = v.z;
            As[kq + 3][r] = v.w;
        }
#pragma unroll
        for (int l = 0; l < 4; l++) {
            int i = t + l * 256;
            reinterpret_cast<float4*>(&Bs[0][0])[i] =
                reinterpret_cast<const float4*>(&W[(size_t)k0 * DIM])[i];
        }
        __syncthreads();

#pragma unroll
        for (int k = 0; k < 32; k++) {
            float a[8], b[4];
#pragma unroll
            for (int i = 0; i < 8; i++) a[i] = As[k][tm * 8 + i];
            float4 bv = *reinterpret_cast<const float4*>(&Bs[k][tn * 4]);
            b[0] = bv.x; b[1] = bv.y; b[2] = bv.z; b[3] = bv.w;
#pragma unroll
            for (int i = 0; i < 8; i++)
#pragma unroll
                for (int j = 0; j < 4; j++) acc[i][j] += a[i] * b[j];
        }
        __syncthreads();
    }

#pragma unroll
    for (int i = 0; i < 8; i++) {
        int r = row0 + tm * 8 + i;
        if (r < nrows) {
            int dg = degs[r];
            float inv = rsqrtf((float)(dg > 0 ? dg : 1));
            float4 v = make_float4(acc[i][0] * inv, acc[i][1] * inv,
                                   acc[i][2] * inv, acc[i][3] * inv);
            *reinterpret_cast<float4*>(&H[(size_t)r * DIM + tn * 4]) = v;
        }
    }
}

// ---------------------------------------------------------------------
// Warp-per-node gather. CSR indices read with streaming hint (__ldcs)
// so they don't evict the L2-resident h rows.
// ---------------------------------------------------------------------
__device__ __forceinline__ float4 gather_accum(const int* __restrict__ csr,
                                               int start, int cnt,
                                               const float* __restrict__ h, int lane) {
    float4 acc = make_float4(0.f, 0.f, 0.f, 0.f);
    int j = 0;
    while (j < cnt) {
        int m = min(32, cnt - j);
        int idx = (lane < m) ? __ldcs(&csr[start + j + lane]) : 0;
#pragma unroll 4
        for (int k = 0; k < m; k++) {
            int s = __shfl_sync(0xffffffffu, idx, k);
            float4 v = *reinterpret_cast<const float4*>(&h[(size_t)s * DIM + lane * 4]);
            acc.x += v.x; acc.y += v.y; acc.z += v.z; acc.w += v.w;
        }
        j += m;
    }
    return acc;
}

// Phase A: a-nodes only (reads h_ba + h_aa, 76 MB footprint -> L2)
__global__ __launch_bounds__(256) void gather_a_kernel(float* __restrict__ out_a) {
    int gw = blockIdx.x * (blockDim.x >> 5) + (threadIdx.x >> 5);
    int lane = threadIdx.x & 31;
    if (gw >= NA) return;
    int d = gw;
    int c_ba = g_deg_t_ba[d];
    int c_aa = g_deg_t_aa[d];
    float4 s_ba = gather_accum(g_csr_ba, g_rs_ba[d], c_ba, g_h_ba, lane);
    float4 s_aa = gather_accum(g_csr_aa, g_rs_aa[d], c_aa, g_h_aa, lane);
    float rb = (c_ba > 0) ? rsqrtf((float)c_ba) * 0.5f : 0.f;
    float ra = (c_aa > 0) ? rsqrtf((float)c_aa) * 0.5f : 0.f;
    float4 v;
    v.x = fmaxf(s_ba.x * rb + s_aa.x * ra, 0.f);
    v.y = fmaxf(s_ba.y * rb + s_aa.y * ra, 0.f);
    v.z = fmaxf(s_ba.z * rb + s_aa.z * ra, 0.f);
    v.w = fmaxf(s_ba.w * rb + s_aa.w * ra, 0.f);
    __stcs(reinterpret_cast<float4*>(&out_a[(size_t)d * DIM + lane * 4]), v);
}

// Phase B: b-nodes only (reads h_ab, 51 MB footprint -> L2)
__global__ __launch_bounds__(256) void gather_b_kernel(float* __restrict__ out_b) {
    int gw = blockIdx.x * (blockDim.x >> 5) + (threadIdx.x >> 5);
    int lane = threadIdx.x & 31;
    if (gw >= NB) return;
    int d = gw;
    int c_ab = g_deg_t_ab[d];
    float4 s_ab = gather_accum(g_csr_ab, g_rs_ab[d], c_ab, g_h_ab, lane);
    float r = (c_ab > 0) ? rsqrtf((float)c_ab) : 0.f;
    float4 v;
    v.x = fmaxf(s_ab.x * r, 0.f);
    v.y = fmaxf(s_ab.y * r, 0.f);
    v.z = fmaxf(s_ab.z * r, 0.f);
    v.w = fmaxf(s_ab.w * r, 0.f);
    __stcs(reinterpret_cast<float4*>(&out_b[(size_t)d * DIM + lane * 4]), v);
}

// ---------------------------------------------------------------------
extern "C" void kernel_launch(void* const* d_in, const int* in_sizes, int n_in,
                              void* d_out, int out_size) {
    const float* x_a  = (const float*)d_in[0];
    const float* x_b  = (const float*)d_in[1];
    const float* W_ab = (const float*)d_in[2];
    const float* W_ba = (const float*)d_in[3];
    const float* W_aa = (const float*)d_in[4];
    const int* src_ab = (const int*)d_in[5];
    const int* dst_ab = (const int*)d_in[6];
    const int* src_ba = (const int*)d_in[7];
    const int* dst_ba = (const int*)d_in[8];
    const int* src_aa = (const int*)d_in[9];
    const int* dst_aa = (const int*)d_in[10];

    float* out   = (float*)d_out;
    float* out_a = out;                       // [NA,128]
    float* out_b = out + (size_t)NA * DIM;    // [NB,128]

    float *h_ab, *h_ba, *h_aa;
    cudaGetSymbolAddress((void**)&h_ab, g_h_ab);
    cudaGetSymbolAddress((void**)&h_ba, g_h_ba);
    cudaGetSymbolAddress((void**)&h_aa, g_h_aa);

    int *d_s_ab, *d_s_ba, *d_s_aa;
    cudaGetSymbolAddress((void**)&d_s_ab, g_deg_s_ab);
    cudaGetSymbolAddress((void**)&d_s_ba, g_deg_s_ba);
    cudaGetSymbolAddress((void**)&d_s_aa, g_deg_s_aa);

    zero_kernel<<<512, 256>>>();

    degree_kernel<<<(EE + 255) / 256, 256>>>(src_ab, dst_ab, src_ba, dst_ba, src_aa, dst_aa);

    scan3_kernel<<<3, 1024>>>();

    fill_kernel<<<(EE + 255) / 256, 256>>>(src_ab, dst_ab, src_ba, dst_ba, src_aa, dst_aa);

    // Phase A: produce h_ba + h_aa (76 MB, lands hot in L2), then gather a-nodes.
    gemm128_kernel<<<(NB + 63) / 64, 256>>>(x_b, W_ba, h_ba, d_s_ba, NB);
    gemm128_kernel<<<(NA + 63) / 64, 256>>>(x_a, W_aa, h_aa, d_s_aa, NA);
    {
        int blocks = (NA + 7) / 8;
        gather_a_kernel<<<blocks, 256>>>(out_a);
    }

    // Phase B: produce h_ab (51 MB, hot in L2), then gather b-nodes.
    gemm128_kernel<<<(NA + 63) / 64, 256>>>(x_a, W_ab, h_ab, d_s_ab, NA);
    {
        int blocks = (NB + 7) / 8;
        gather_b_kernel<<<blocks, 256>>>(out_b);
    }
}

// round 7
// speedup vs baseline: 1.1255x; 1.0278x over previous
#include <cuda_runtime.h>
#include <cuda_bf16.h>

#define NA 100000
#define NB 50000
#define DIM 128
#define EE 1000000

// ---- static device scratch ----
__device__ float g_h_ab[(size_t)NA * DIM];   // (x_a @ W_ab) * rsqrt(deg_s_ab)  -> out_b
__device__ float g_h_ba[(size_t)NB * DIM];   // (x_b @ W_ba) * rsqrt(deg_s_ba)  -> out_a
__device__ float g_h_aa[(size_t)NA * DIM];   // (x_a @ W_aa) * rsqrt(deg_s_aa)  -> out_a

__device__ int g_deg_s_ab[NA];
__device__ int g_deg_t_ab[NB];
__device__ int g_deg_s_ba[NB];
__device__ int g_deg_t_ba[NA];
__device__ int g_deg_s_aa[NA];
__device__ int g_deg_t_aa[NA];

// CSR-by-dst
__device__ int g_rs_ab[NB];
__device__ int g_rs_ba[NA];
__device__ int g_rs_aa[NA];
__device__ int g_cur_ab[NB];
__device__ int g_cur_ba[NA];
__device__ int g_cur_aa[NA];
__device__ int g_csr_ab[EE];
__device__ int g_csr_ba[EE];
__device__ int g_csr_aa[EE];

// ---------------------------------------------------------------------
__global__ void zero_kernel() {
    int i = blockIdx.x * blockDim.x + threadIdx.x;
    int stride = gridDim.x * blockDim.x;
    for (int j = i; j < NA; j += stride) {
        g_deg_s_ab[j] = 0;
        g_deg_t_ba[j] = 0;
        g_deg_s_aa[j] = 0;
        g_deg_t_aa[j] = 0;
    }
    for (int j = i; j < NB; j += stride) {
        g_deg_t_ab[j] = 0;
        g_deg_s_ba[j] = 0;
    }
}

// ---------------------------------------------------------------------
// Degree histograms for all 3 edge types (src + dst)
// ---------------------------------------------------------------------
__global__ void degree_kernel(const int* __restrict__ src_ab, const int* __restrict__ dst_ab,
                              const int* __restrict__ src_ba, const int* __restrict__ dst_ba,
                              const int* __restrict__ src_aa, const int* __restrict__ dst_aa) {
    int i = blockIdx.x * blockDim.x + threadIdx.x;
    if (i >= EE) return;
    atomicAdd(&g_deg_s_ab[src_ab[i]], 1);
    atomicAdd(&g_deg_t_ab[dst_ab[i]], 1);
    atomicAdd(&g_deg_s_ba[src_ba[i]], 1);
    atomicAdd(&g_deg_t_ba[dst_ba[i]], 1);
    atomicAdd(&g_deg_s_aa[src_aa[i]], 1);
    atomicAdd(&g_deg_t_aa[dst_aa[i]], 1);
}

// ---------------------------------------------------------------------
// Exclusive scan of the 3 dst-degree arrays (one block per array).
// ---------------------------------------------------------------------
__global__ __launch_bounds__(1024) void scan3_kernel() {
    const int* deg;
    int n;
    int* rs;
    int* cur;
    if (blockIdx.x == 0)      { deg = g_deg_t_ab; n = NB; rs = g_rs_ab; cur = g_cur_ab; }
    else if (blockIdx.x == 1) { deg = g_deg_t_ba; n = NA; rs = g_rs_ba; cur = g_cur_ba; }
    else                      { deg = g_deg_t_aa; n = NA; rs = g_rs_aa; cur = g_cur_aa; }

    const int t = threadIdx.x;
    const int chunk = (n + 1023) >> 10;
    const int lo = t * chunk;
    const int hi = min(lo + chunk, n);

    int s = 0;
    for (int i = lo; i < hi; i++) s += deg[i];

    __shared__ int sm[1024];
    sm[t] = s;
    __syncthreads();
    for (int off = 1; off < 1024; off <<= 1) {
        int v = (t >= off) ? sm[t - off] : 0;
        __syncthreads();
        sm[t] += v;
        __syncthreads();
    }
    int base = (t > 0) ? sm[t - 1] : 0;
    for (int i = lo; i < hi; i++) {
        rs[i] = base;
        cur[i] = base;
        base += deg[i];
    }
}

// ---------------------------------------------------------------------
// Fill CSR buckets (order within a bucket irrelevant for a sum)
// ---------------------------------------------------------------------
__global__ void fill_kernel(const int* __restrict__ src_ab, const int* __restrict__ dst_ab,
                            const int* __restrict__ src_ba, const int* __restrict__ dst_ba,
                            const int* __restrict__ src_aa, const int* __restrict__ dst_aa) {
    int i = blockIdx.x * blockDim.x + threadIdx.x;
    if (i >= EE) return;
    int p;
    p = atomicAdd(&g_cur_ab[dst_ab[i]], 1); g_csr_ab[p] = src_ab[i];
    p = atomicAdd(&g_cur_ba[dst_ba[i]], 1); g_csr_ba[p] = src_ba[i];
    p = atomicAdd(&g_cur_aa[dst_aa[i]], 1); g_csr_aa[p] = src_aa[i];
}

// ---------------------------------------------------------------------
// SGEMM with packed f32x2 FMA: H = (X @ W) * rsqrt(deg_s[row])
// BM=64, BN=128, BK=32, 256 threads. Per-thread: 4 row-pairs x 4 cols,
// fma.rn.f32x2 = 2 exact fp32 FMAs per fma-pipe issue.
// ---------------------------------------------------------------------
__global__ __launch_bounds__(256) void gemm128_kernel(const float* __restrict__ X,
                                                      const float* __restrict__ W,
                                                      float* __restrict__ H,
                                                      const int* __restrict__ degs,
                                                      int nrows) {
    __shared__ float As[32][66];    // [k][m], even stride -> 8B-aligned row pairs
    __shared__ float Bs[32][128];   // [k][n]

    const int t = threadIdx.x;
    const int tn = t & 31;   // col group (4 cols)
    const int tm = t >> 5;   // row group (8 rows = 4 pairs)
    const int row0 = blockIdx.x * 64;

    unsigned long long acc2[4][4];  // [row-pair][col]
#pragma unroll
    for (int i = 0; i < 4; i++)
#pragma unroll
        for (int j = 0; j < 4; j++) acc2[i][j] = 0ull;

    for (int k0 = 0; k0 < 128; k0 += 32) {
        // A tile: 64 rows x 32 k
#pragma unroll
        for (int l = 0; l < 2; l++) {
            int i = t + l * 256;
            int r = i >> 3;
            int kq = (i & 7) * 4;
            float4 v = make_float4(0.f, 0.f, 0.f, 0.f);
            if (row0 + r < nrows)
                v = *reinterpret_cast<const float4*>(&X[(size_t)(row0 + r) * DIM + k0 + kq]);
            As[kq + 0][r] = v.x;
            As[kq + 1][r] = v.y;
            As[kq + 2][r] = v.z;
            As[kq + 3][r] = v.w;
        }
        // B tile: 32 k x 128 n
#pragma unroll
        for (int l = 0; l < 4; l++) {
            int i = t + l * 256;
            reinterpret_cast<float4*>(&Bs[0][0])[i] =
                reinterpret_cast<const float4*>(&W[(size_t)k0 * DIM])[i];
        }
        __syncthreads();

#pragma unroll
        for (int k = 0; k < 32; k++) {
            // 4 row-pairs of A (8B-aligned, compiler-scheduled LDS.64)
            const unsigned long long* ap =
                reinterpret_cast<const unsigned long long*>(&As[k][tm * 8]);
            unsigned long long a2[4];
#pragma unroll
            for (int ii = 0; ii < 4; ii++) a2[ii] = ap[ii];

            float4 bv = *reinterpret_cast<const float4*>(&Bs[k][tn * 4]);
            unsigned long long bd[4];
            asm("mov.b64 %0, {%1, %1};" : "=l"(bd[0]) : "f"(bv.x));
            asm("mov.b64 %0, {%1, %1};" : "=l"(bd[1]) : "f"(bv.y));
            asm("mov.b64 %0, {%1, %1};" : "=l"(bd[2]) : "f"(bv.z));
            asm("mov.b64 %0, {%1, %1};" : "=l"(bd[3]) : "f"(bv.w));
#pragma unroll
            for (int ii = 0; ii < 4; ii++)
#pragma unroll
                for (int j = 0; j < 4; j++)
                    asm("fma.rn.f32x2 %0, %1, %2, %0;"
                        : "+l"(acc2[ii][j]) : "l"(a2[ii]), "l"(bd[j]));
        }
        __syncthreads();
    }

#pragma unroll
    for (int ii = 0; ii < 4; ii++) {
        float lo[4], hi[4];
#pragma unroll
        for (int j = 0; j < 4; j++)
            asm("mov.b64 {%0, %1}, %2;" : "=f"(lo[j]), "=f"(hi[j]) : "l"(acc2[ii][j]));
        int r0 = row0 + tm * 8 + 2 * ii;
        if (r0 < nrows) {
            int dg = degs[r0];
            float inv = rsqrtf((float)(dg > 0 ? dg : 1));
            float4 v = make_float4(lo[0] * inv, lo[1] * inv, lo[2] * inv, lo[3] * inv);
            *reinterpret_cast<float4*>(&H[(size_t)r0 * DIM + tn * 4]) = v;
        }
        int r1 = r0 + 1;
        if (r1 < nrows) {
            int dg = degs[r1];
            float inv = rsqrtf((float)(dg > 0 ? dg : 1));
            float4 v = make_float4(hi[0] * inv, hi[1] * inv, hi[2] * inv, hi[3] * inv);
            *reinterpret_cast<float4*>(&H[(size_t)r1 * DIM + tn * 4]) = v;
        }
    }
}

// ---------------------------------------------------------------------
// Warp-per-node gather. CSR indices read with streaming hint (__ldcs).
// ---------------------------------------------------------------------
__device__ __forceinline__ float4 gather_accum(const int* __restrict__ csr,
                                               int start, int cnt,
                                               const float* __restrict__ h, int lane) {
    float4 acc = make_float4(0.f, 0.f, 0.f, 0.f);
    int j = 0;
    while (j < cnt) {
        int m = min(32, cnt - j);
        int idx = (lane < m) ? __ldcs(&csr[start + j + lane]) : 0;
#pragma unroll 4
        for (int k = 0; k < m; k++) {
            int s = __shfl_sync(0xffffffffu, idx, k);
            float4 v = *reinterpret_cast<const float4*>(&h[(size_t)s * DIM + lane * 4]);
            acc.x += v.x; acc.y += v.y; acc.z += v.z; acc.w += v.w;
        }
        j += m;
    }
    return acc;
}

// Phase A: a-nodes only (reads h_ba + h_aa)
__global__ __launch_bounds__(256) void gather_a_kernel(float* __restrict__ out_a) {
    int gw = blockIdx.x * (blockDim.x >> 5) + (threadIdx.x >> 5);
    int lane = threadIdx.x & 31;
    if (gw >= NA) return;
    int d = gw;
    int c_ba = g_deg_t_ba[d];
    int c_aa = g_deg_t_aa[d];
    float4 s_ba = gather_accum(g_csr_ba, g_rs_ba[d], c_ba, g_h_ba, lane);
    float4 s_aa = gather_accum(g_csr_aa, g_rs_aa[d], c_aa, g_h_aa, lane);
    float rb = (c_ba > 0) ? rsqrtf((float)c_ba) * 0.5f : 0.f;
    float ra = (c_aa > 0) ? rsqrtf((float)c_aa) * 0.5f : 0.f;
    float4 v;
    v.x = fmaxf(s_ba.x * rb + s_aa.x * ra, 0.f);
    v.y = fmaxf(s_ba.y * rb + s_aa.y * ra, 0.f);
    v.z = fmaxf(s_ba.z * rb + s_aa.z * ra, 0.f);
    v.w = fmaxf(s_ba.w * rb + s_aa.w * ra, 0.f);
    __stcs(reinterpret_cast<float4*>(&out_a[(size_t)d * DIM + lane * 4]), v);
}

// Phase B: b-nodes only (reads h_ab)
__global__ __launch_bounds__(256) void gather_b_kernel(float* __restrict__ out_b) {
    int gw = blockIdx.x * (blockDim.x >> 5) + (threadIdx.x >> 5);
    int lane = threadIdx.x & 31;
    if (gw >= NB) return;
    int d = gw;
    int c_ab = g_deg_t_ab[d];
    float4 s_ab = gather_accum(g_csr_ab, g_rs_ab[d], c_ab, g_h_ab, lane);
    float r = (c_ab > 0) ? rsqrtf((float)c_ab) : 0.f;
    float4 v;
    v.x = fmaxf(s_ab.x * r, 0.f);
    v.y = fmaxf(s_ab.y * r, 0.f);
    v.z = fmaxf(s_ab.z * r, 0.f);
    v.w = fmaxf(s_ab.w * r, 0.f);
    __stcs(reinterpret_cast<float4*>(&out_b[(size_t)d * DIM + lane * 4]), v);
}

// ---------------------------------------------------------------------
extern "C" void kernel_launch(void* const* d_in, const int* in_sizes, int n_in,
                              void* d_out, int out_size) {
    const float* x_a  = (const float*)d_in[0];
    const float* x_b  = (const float*)d_in[1];
    const float* W_ab = (const float*)d_in[2];
    const float* W_ba = (const float*)d_in[3];
    const float* W_aa = (const float*)d_in[4];
    const int* src_ab = (const int*)d_in[5];
    const int* dst_ab = (const int*)d_in[6];
    const int* src_ba = (const int*)d_in[7];
    const int* dst_ba = (const int*)d_in[8];
    const int* src_aa = (const int*)d_in[9];
    const int* dst_aa = (const int*)d_in[10];

    float* out   = (float*)d_out;
    float* out_a = out;                       // [NA,128]
    float* out_b = out + (size_t)NA * DIM;    // [NB,128]

    float *h_ab, *h_ba, *h_aa;
    cudaGetSymbolAddress((void**)&h_ab, g_h_ab);
    cudaGetSymbolAddress((void**)&h_ba, g_h_ba);
    cudaGetSymbolAddress((void**)&h_aa, g_h_aa);

    int *d_s_ab, *d_s_ba, *d_s_aa;
    cudaGetSymbolAddress((void**)&d_s_ab, g_deg_s_ab);
    cudaGetSymbolAddress((void**)&d_s_ba, g_deg_s_ba);
    cudaGetSymbolAddress((void**)&d_s_aa, g_deg_s_aa);

    zero_kernel<<<512, 256>>>();

    degree_kernel<<<(EE + 255) / 256, 256>>>(src_ab, dst_ab, src_ba, dst_ba, src_aa, dst_aa);

    scan3_kernel<<<3, 1024>>>();

    fill_kernel<<<(EE + 255) / 256, 256>>>(src_ab, dst_ab, src_ba, dst_ba, src_aa, dst_aa);

    // Phase A: produce h_ba + h_aa, then gather a-nodes.
    gemm128_kernel<<<(NB + 63) / 64, 256>>>(x_b, W_ba, h_ba, d_s_ba, NB);
    gemm128_kernel<<<(NA + 63) / 64, 256>>>(x_a, W_aa, h_aa, d_s_aa, NA);
    {
        int blocks = (NA + 7) / 8;
        gather_a_kernel<<<blocks, 256>>>(out_a);
    }

    // Phase B: produce h_ab, then gather b-nodes.
    gemm128_kernel<<<(NA + 63) / 64, 256>>>(x_a, W_ab, h_ab, d_s_ab, NA);
    {
        int blocks = (NB + 7) / 8;
        gather_b_kernel<<<blocks, 256>>>(out_b);
    }
}

// round 8
// speedup vs baseline: 1.2036x; 1.0694x over previous
#include <cuda_runtime.h>
#include <cuda_bf16.h>

#define NA 100000
#define NB 50000
#define DIM 128
#define EE 1000000

// ---- static device scratch ----
__device__ float g_h_ab[(size_t)NA * DIM];   // x_a @ W_ab  -> out_b
__device__ float g_h_ba[(size_t)NB * DIM];   // x_b @ W_ba  -> out_a
__device__ float g_h_aa[(size_t)NA * DIM];   // x_a @ W_aa  -> out_a

__device__ int g_deg_s_ab[NA];
__device__ int g_deg_t_ab[NB];
__device__ int g_deg_s_ba[NB];
__device__ int g_deg_t_ba[NA];
__device__ int g_deg_s_aa[NA];
__device__ int g_deg_t_aa[NA];

// CSR-by-dst
__device__ int g_rs_ab[NB];
__device__ int g_rs_ba[NA];
__device__ int g_rs_aa[NA];
__device__ int g_cur_ab[NB];
__device__ int g_cur_ba[NA];
__device__ int g_cur_aa[NA];
__device__ int g_csr_ab[EE];
__device__ int g_csr_ba[EE];
__device__ int g_csr_aa[EE];

// ---- streams/events for fork-join overlap (created once at load; no device mem) ----
static cudaStream_t g_s1;
static cudaEvent_t g_evFork, g_evGemmA, g_evCsr, g_evTailB;
static struct InitOnce {
    InitOnce() {
        cudaStreamCreateWithFlags(&g_s1, cudaStreamNonBlocking);
        cudaEventCreateWithFlags(&g_evFork, cudaEventDisableTiming);
        cudaEventCreateWithFlags(&g_evGemmA, cudaEventDisableTiming);
        cudaEventCreateWithFlags(&g_evCsr, cudaEventDisableTiming);
        cudaEventCreateWithFlags(&g_evTailB, cudaEventDisableTiming);
    }
} g_initOnce;

// ---------------------------------------------------------------------
__global__ void zero_kernel() {
    int i = blockIdx.x * blockDim.x + threadIdx.x;
    int stride = gridDim.x * blockDim.x;
    for (int j = i; j < NA; j += stride) {
        g_deg_s_ab[j] = 0;
        g_deg_t_ba[j] = 0;
        g_deg_s_aa[j] = 0;
        g_deg_t_aa[j] = 0;
    }
    for (int j = i; j < NB; j += stride) {
        g_deg_t_ab[j] = 0;
        g_deg_s_ba[j] = 0;
    }
}

// ---------------------------------------------------------------------
// Degree histograms (src + dst) for all 3 edge types
// ---------------------------------------------------------------------
__global__ void degree_kernel(const int* __restrict__ src_ab, const int* __restrict__ dst_ab,
                              const int* __restrict__ src_ba, const int* __restrict__ dst_ba,
                              const int* __restrict__ src_aa, const int* __restrict__ dst_aa) {
    int i = blockIdx.x * blockDim.x + threadIdx.x;
    if (i >= EE) return;
    atomicAdd(&g_deg_s_ab[src_ab[i]], 1);
    atomicAdd(&g_deg_t_ab[dst_ab[i]], 1);
    atomicAdd(&g_deg_s_ba[src_ba[i]], 1);
    atomicAdd(&g_deg_t_ba[dst_ba[i]], 1);
    atomicAdd(&g_deg_s_aa[src_aa[i]], 1);
    atomicAdd(&g_deg_t_aa[dst_aa[i]], 1);
}

// ---------------------------------------------------------------------
// Exclusive scan of the 3 dst-degree arrays (one block per array).
// ---------------------------------------------------------------------
__global__ __launch_bounds__(1024) void scan3_kernel() {
    const int* deg;
    int n;
    int* rs;
    int* cur;
    if (blockIdx.x == 0)      { deg = g_deg_t_ab; n = NB; rs = g_rs_ab; cur = g_cur_ab; }
    else if (blockIdx.x == 1) { deg = g_deg_t_ba; n = NA; rs = g_rs_ba; cur = g_cur_ba; }
    else                      { deg = g_deg_t_aa; n = NA; rs = g_rs_aa; cur = g_cur_aa; }

    const int t = threadIdx.x;
    const int chunk = (n + 1023) >> 10;
    const int lo = t * chunk;
    const int hi = min(lo + chunk, n);

    int s = 0;
    for (int i = lo; i < hi; i++) s += deg[i];

    __shared__ int sm[1024];
    sm[t] = s;
    __syncthreads();
    for (int off = 1; off < 1024; off <<= 1) {
        int v = (t >= off) ? sm[t - off] : 0;
        __syncthreads();
        sm[t] += v;
        __syncthreads();
    }
    int base = (t > 0) ? sm[t - 1] : 0;
    for (int i = lo; i < hi; i++) {
        rs[i] = base;
        cur[i] = base;
        base += deg[i];
    }
}

// ---------------------------------------------------------------------
// Fill CSR buckets
// ---------------------------------------------------------------------
__global__ void fill_kernel(const int* __restrict__ src_ab, const int* __restrict__ dst_ab,
                            const int* __restrict__ src_ba, const int* __restrict__ dst_ba,
                            const int* __restrict__ src_aa, const int* __restrict__ dst_aa) {
    int i = blockIdx.x * blockDim.x + threadIdx.x;
    if (i >= EE) return;
    int p;
    p = atomicAdd(&g_cur_ab[dst_ab[i]], 1); g_csr_ab[p] = src_ab[i];
    p = atomicAdd(&g_cur_ba[dst_ba[i]], 1); g_csr_ba[p] = src_ba[i];
    p = atomicAdd(&g_cur_aa[dst_aa[i]], 1); g_csr_aa[p] = src_aa[i];
}

// ---------------------------------------------------------------------
// SGEMM (f32x2): H = X @ W   (no degree scaling -> independent of degrees)
// BM=64, BN=128, BK=32, 256 threads, 4 row-pairs x 4 cols per thread.
// ---------------------------------------------------------------------
__global__ __launch_bounds__(256) void gemm128_kernel(const float* __restrict__ X,
                                                      const float* __restrict__ W,
                                                      float* __restrict__ H,
                                                      int nrows) {
    __shared__ float As[32][66];
    __shared__ float Bs[32][128];

    const int t = threadIdx.x;
    const int tn = t & 31;
    const int tm = t >> 5;
    const int row0 = blockIdx.x * 64;

    unsigned long long acc2[4][4];
#pragma unroll
    for (int i = 0; i < 4; i++)
#pragma unroll
        for (int j = 0; j < 4; j++) acc2[i][j] = 0ull;

    for (int k0 = 0; k0 < 128; k0 += 32) {
#pragma unroll
        for (int l = 0; l < 2; l++) {
            int i = t + l * 256;
            int r = i >> 3;
            int kq = (i & 7) * 4;
            float4 v = make_float4(0.f, 0.f, 0.f, 0.f);
            if (row0 + r < nrows)
                v = *reinterpret_cast<const float4*>(&X[(size_t)(row0 + r) * DIM + k0 + kq]);
            As[kq + 0][r] = v.x;
            As[kq + 1][r] = v.y;
            As[kq + 2][r] = v.z;
            As[kq + 3][r] = v.w;
        }
#pragma unroll
        for (int l = 0; l < 4; l++) {
            int i = t + l * 256;
            reinterpret_cast<float4*>(&Bs[0][0])[i] =
                reinterpret_cast<const float4*>(&W[(size_t)k0 * DIM])[i];
        }
        __syncthreads();

#pragma unroll
        for (int k = 0; k < 32; k++) {
            const unsigned long long* ap =
                reinterpret_cast<const unsigned long long*>(&As[k][tm * 8]);
            unsigned long long a2[4];
#pragma unroll
            for (int ii = 0; ii < 4; ii++) a2[ii] = ap[ii];

            float4 bv = *reinterpret_cast<const float4*>(&Bs[k][tn * 4]);
            unsigned long long bd[4];
            asm("mov.b64 %0, {%1, %1};" : "=l"(bd[0]) : "f"(bv.x));
            asm("mov.b64 %0, {%1, %1};" : "=l"(bd[1]) : "f"(bv.y));
            asm("mov.b64 %0, {%1, %1};" : "=l"(bd[2]) : "f"(bv.z));
            asm("mov.b64 %0, {%1, %1};" : "=l"(bd[3]) : "f"(bv.w));
#pragma unroll
            for (int ii = 0; ii < 4; ii++)
#pragma unroll
                for (int j = 0; j < 4; j++)
                    asm("fma.rn.f32x2 %0, %1, %2, %0;"
                        : "+l"(acc2[ii][j]) : "l"(a2[ii]), "l"(bd[j]));
        }
        __syncthreads();
    }

#pragma unroll
    for (int ii = 0; ii < 4; ii++) {
        float lo[4], hi[4];
#pragma unroll
        for (int j = 0; j < 4; j++)
            asm("mov.b64 {%0, %1}, %2;" : "=f"(lo[j]), "=f"(hi[j]) : "l"(acc2[ii][j]));
        int r0 = row0 + tm * 8 + 2 * ii;
        if (r0 < nrows)
            *reinterpret_cast<float4*>(&H[(size_t)r0 * DIM + tn * 4]) =
                make_float4(lo[0], lo[1], lo[2], lo[3]);
        int r1 = r0 + 1;
        if (r1 < nrows)
            *reinterpret_cast<float4*>(&H[(size_t)r1 * DIM + tn * 4]) =
                make_float4(hi[0], hi[1], hi[2], hi[3]);
    }
}

// ---------------------------------------------------------------------
// Warp-per-node gather; per-edge rsqrt(deg_s[src]) applied here.
// ---------------------------------------------------------------------
__device__ __forceinline__ float4 gather_accum(const int* __restrict__ csr,
                                               const int* __restrict__ deg_s,
                                               int start, int cnt,
                                               const float* __restrict__ h, int lane) {
    float4 acc = make_float4(0.f, 0.f, 0.f, 0.f);
    int j = 0;
    while (j < cnt) {
        int m = min(32, cnt - j);
        int idx = 0;
        float inv = 0.f;
        if (lane < m) {
            idx = __ldcs(&csr[start + j + lane]);
            inv = rsqrtf((float)deg_s[idx]);
        }
#pragma unroll 4
        for (int k = 0; k < m; k++) {
            int s = __shfl_sync(0xffffffffu, idx, k);
            float iv = __shfl_sync(0xffffffffu, inv, k);
            float4 v = *reinterpret_cast<const float4*>(&h[(size_t)s * DIM + lane * 4]);
            acc.x += v.x * iv; acc.y += v.y * iv; acc.z += v.z * iv; acc.w += v.w * iv;
        }
        j += m;
    }
    return acc;
}

// a-nodes: combine ba + aa
__global__ __launch_bounds__(256) void gather_a_kernel(float* __restrict__ out_a) {
    int gw = blockIdx.x * (blockDim.x >> 5) + (threadIdx.x >> 5);
    int lane = threadIdx.x & 31;
    if (gw >= NA) return;
    int d = gw;
    int c_ba = g_deg_t_ba[d];
    int c_aa = g_deg_t_aa[d];
    float4 s_ba = gather_accum(g_csr_ba, g_deg_s_ba, g_rs_ba[d], c_ba, g_h_ba, lane);
    float4 s_aa = gather_accum(g_csr_aa, g_deg_s_aa, g_rs_aa[d], c_aa, g_h_aa, lane);
    float rb = (c_ba > 0) ? rsqrtf((float)c_ba) * 0.5f : 0.f;
    float ra = (c_aa > 0) ? rsqrtf((float)c_aa) * 0.5f : 0.f;
    float4 v;
    v.x = fmaxf(s_ba.x * rb + s_aa.x * ra, 0.f);
    v.y = fmaxf(s_ba.y * rb + s_aa.y * ra, 0.f);
    v.z = fmaxf(s_ba.z * rb + s_aa.z * ra, 0.f);
    v.w = fmaxf(s_ba.w * rb + s_aa.w * ra, 0.f);
    __stcs(reinterpret_cast<float4*>(&out_a[(size_t)d * DIM + lane * 4]), v);
}

// b-nodes: ab only
__global__ __launch_bounds__(256) void gather_b_kernel(float* __restrict__ out_b) {
    int gw = blockIdx.x * (blockDim.x >> 5) + (threadIdx.x >> 5);
    int lane = threadIdx.x & 31;
    if (gw >= NB) return;
    int d = gw;
    int c_ab = g_deg_t_ab[d];
    float4 s_ab = gather_accum(g_csr_ab, g_deg_s_ab, g_rs_ab[d], c_ab, g_h_ab, lane);
    float r = (c_ab > 0) ? rsqrtf((float)c_ab) : 0.f;
    float4 v;
    v.x = fmaxf(s_ab.x * r, 0.f);
    v.y = fmaxf(s_ab.y * r, 0.f);
    v.z = fmaxf(s_ab.z * r, 0.f);
    v.w = fmaxf(s_ab.w * r, 0.f);
    __stcs(reinterpret_cast<float4*>(&out_b[(size_t)d * DIM + lane * 4]), v);
}

// ---------------------------------------------------------------------
extern "C" void kernel_launch(void* const* d_in, const int* in_sizes, int n_in,
                              void* d_out, int out_size) {
    const float* x_a  = (const float*)d_in[0];
    const float* x_b  = (const float*)d_in[1];
    const float* W_ab = (const float*)d_in[2];
    const float* W_ba = (const float*)d_in[3];
    const float* W_aa = (const float*)d_in[4];
    const int* src_ab = (const int*)d_in[5];
    const int* dst_ab = (const int*)d_in[6];
    const int* src_ba = (const int*)d_in[7];
    const int* dst_ba = (const int*)d_in[8];
    const int* src_aa = (const int*)d_in[9];
    const int* dst_aa = (const int*)d_in[10];

    float* out   = (float*)d_out;
    float* out_a = out;                       // [NA,128]
    float* out_b = out + (size_t)NA * DIM;    // [NB,128]

    float *h_ab, *h_ba, *h_aa;
    cudaGetSymbolAddress((void**)&h_ab, g_h_ab);
    cudaGetSymbolAddress((void**)&h_ba, g_h_ba);
    cudaGetSymbolAddress((void**)&h_aa, g_h_aa);

    // ---- fork: side stream runs the 3 GEMMs (no degree dependency) ----
    cudaEventRecord(g_evFork, 0);
    cudaStreamWaitEvent(g_s1, g_evFork, 0);

    gemm128_kernel<<<(NB + 63) / 64, 256, 0, g_s1>>>(x_b, W_ba, h_ba, NB);
    gemm128_kernel<<<(NA + 63) / 64, 256, 0, g_s1>>>(x_a, W_aa, h_aa, NA);
    cudaEventRecord(g_evGemmA, g_s1);                    // h_ba + h_aa ready
    gemm128_kernel<<<(NA + 63) / 64, 256, 0, g_s1>>>(x_a, W_ab, h_ab, NA);

    // ---- main stream: CSR build ----
    zero_kernel<<<512, 256>>>();
    degree_kernel<<<(EE + 255) / 256, 256>>>(src_ab, dst_ab, src_ba, dst_ba, src_aa, dst_aa);
    scan3_kernel<<<3, 1024>>>();
    fill_kernel<<<(EE + 255) / 256, 256>>>(src_ab, dst_ab, src_ba, dst_ba, src_aa, dst_aa);
    cudaEventRecord(g_evCsr, 0);                         // CSR + degrees ready

    // gather_a on main stream: needs CSR (in-stream) + h_ba/h_aa (event)
    cudaStreamWaitEvent(0, g_evGemmA, 0);
    gather_a_kernel<<<(NA + 7) / 8, 256>>>(out_a);

    // gather_b on side stream: needs h_ab (in-stream) + CSR (event)
    cudaStreamWaitEvent(g_s1, g_evCsr, 0);
    gather_b_kernel<<<(NB + 7) / 8, 256, 0, g_s1>>>(out_b);
    cudaEventRecord(g_evTailB, g_s1);

    // join
    cudaStreamWaitEvent(0, g_evTailB, 0);
}

// round 9
// speedup vs baseline: 1.5305x; 1.2715x over previous
#include <cuda_runtime.h>
#include <cuda_bf16.h>
#include <cuda_fp16.h>

#define NA 100000
#define NB 50000
#define DIM 128
#define EE 1000000

// ---- static device scratch ----
// h matrices stored as fp16 (halves gather traffic); accumulation is fp32.
__device__ __half g_h_ab[(size_t)NA * DIM];   // x_a @ W_ab  -> out_b
__device__ __half g_h_ba[(size_t)NB * DIM];   // x_b @ W_ba  -> out_a
__device__ __half g_h_aa[(size_t)NA * DIM];   // x_a @ W_aa  -> out_a

__device__ int g_deg_s_ab[NA];
__device__ int g_deg_t_ab[NB];
__device__ int g_deg_s_ba[NB];
__device__ int g_deg_t_ba[NA];
__device__ int g_deg_s_aa[NA];
__device__ int g_deg_t_aa[NA];

// CSR-by-dst
__device__ int g_rs_ab[NB];
__device__ int g_rs_ba[NA];
__device__ int g_rs_aa[NA];
__device__ int g_cur_ab[NB];
__device__ int g_cur_ba[NA];
__device__ int g_cur_aa[NA];
__device__ int g_csr_ab[EE];
__device__ int g_csr_ba[EE];
__device__ int g_csr_aa[EE];

// ---- streams/events for fork-join overlap ----
static cudaStream_t g_s1;
static cudaEvent_t g_evFork, g_evGemmA, g_evCsr, g_evTailB;
static struct InitOnce {
    InitOnce() {
        cudaStreamCreateWithFlags(&g_s1, cudaStreamNonBlocking);
        cudaEventCreateWithFlags(&g_evFork, cudaEventDisableTiming);
        cudaEventCreateWithFlags(&g_evGemmA, cudaEventDisableTiming);
        cudaEventCreateWithFlags(&g_evCsr, cudaEventDisableTiming);
        cudaEventCreateWithFlags(&g_evTailB, cudaEventDisableTiming);
    }
} g_initOnce;

// ---------------------------------------------------------------------
__global__ void zero_kernel() {
    int i = blockIdx.x * blockDim.x + threadIdx.x;
    int stride = gridDim.x * blockDim.x;
    for (int j = i; j < NA; j += stride) {
        g_deg_s_ab[j] = 0;
        g_deg_t_ba[j] = 0;
        g_deg_s_aa[j] = 0;
        g_deg_t_aa[j] = 0;
    }
    for (int j = i; j < NB; j += stride) {
        g_deg_t_ab[j] = 0;
        g_deg_s_ba[j] = 0;
    }
}

// ---------------------------------------------------------------------
__global__ void degree_kernel(const int* __restrict__ src_ab, const int* __restrict__ dst_ab,
                              const int* __restrict__ src_ba, const int* __restrict__ dst_ba,
                              const int* __restrict__ src_aa, const int* __restrict__ dst_aa) {
    int i = blockIdx.x * blockDim.x + threadIdx.x;
    if (i >= EE) return;
    atomicAdd(&g_deg_s_ab[src_ab[i]], 1);
    atomicAdd(&g_deg_t_ab[dst_ab[i]], 1);
    atomicAdd(&g_deg_s_ba[src_ba[i]], 1);
    atomicAdd(&g_deg_t_ba[dst_ba[i]], 1);
    atomicAdd(&g_deg_s_aa[src_aa[i]], 1);
    atomicAdd(&g_deg_t_aa[dst_aa[i]], 1);
}

// ---------------------------------------------------------------------
__global__ __launch_bounds__(1024) void scan3_kernel() {
    const int* deg;
    int n;
    int* rs;
    int* cur;
    if (blockIdx.x == 0)      { deg = g_deg_t_ab; n = NB; rs = g_rs_ab; cur = g_cur_ab; }
    else if (blockIdx.x == 1) { deg = g_deg_t_ba; n = NA; rs = g_rs_ba; cur = g_cur_ba; }
    else                      { deg = g_deg_t_aa; n = NA; rs = g_rs_aa; cur = g_cur_aa; }

    const int t = threadIdx.x;
    const int chunk = (n + 1023) >> 10;
    const int lo = t * chunk;
    const int hi = min(lo + chunk, n);

    int s = 0;
    for (int i = lo; i < hi; i++) s += deg[i];

    __shared__ int sm[1024];
    sm[t] = s;
    __syncthreads();
    for (int off = 1; off < 1024; off <<= 1) {
        int v = (t >= off) ? sm[t - off] : 0;
        __syncthreads();
        sm[t] += v;
        __syncthreads();
    }
    int base = (t > 0) ? sm[t - 1] : 0;
    for (int i = lo; i < hi; i++) {
        rs[i] = base;
        cur[i] = base;
        base += deg[i];
    }
}

// ---------------------------------------------------------------------
__global__ void fill_kernel(const int* __restrict__ src_ab, const int* __restrict__ dst_ab,
                            const int* __restrict__ src_ba, const int* __restrict__ dst_ba,
                            const int* __restrict__ src_aa, const int* __restrict__ dst_aa) {
    int i = blockIdx.x * blockDim.x + threadIdx.x;
    if (i >= EE) return;
    int p;
    p = atomicAdd(&g_cur_ab[dst_ab[i]], 1); g_csr_ab[p] = src_ab[i];
    p = atomicAdd(&g_cur_ba[dst_ba[i]], 1); g_csr_ba[p] = src_ba[i];
    p = atomicAdd(&g_cur_aa[dst_aa[i]], 1); g_csr_aa[p] = src_aa[i];
}

// ---------------------------------------------------------------------
// SGEMM (f32x2): H(fp16) = X @ W
// BM=64, BN=128, BK=32, 256 threads, 4 row-pairs x 4 cols per thread.
// ---------------------------------------------------------------------
__global__ __launch_bounds__(256) void gemm128_kernel(const float* __restrict__ X,
                                                      const float* __restrict__ W,
                                                      __half* __restrict__ H,
                                                      int nrows) {
    __shared__ float As[32][66];
    __shared__ float Bs[32][128];

    const int t = threadIdx.x;
    const int tn = t & 31;
    const int tm = t >> 5;
    const int row0 = blockIdx.x * 64;

    unsigned long long acc2[4][4];
#pragma unroll
    for (int i = 0; i < 4; i++)
#pragma unroll
        for (int j = 0; j < 4; j++) acc2[i][j] = 0ull;

    for (int k0 = 0; k0 < 128; k0 += 32) {
#pragma unroll
        for (int l = 0; l < 2; l++) {
            int i = t + l * 256;
            int r = i >> 3;
            int kq = (i & 7) * 4;
            float4 v = make_float4(0.f, 0.f, 0.f, 0.f);
            if (row0 + r < nrows)
                v = *reinterpret_cast<const float4*>(&X[(size_t)(row0 + r) * DIM + k0 + kq]);
            As[kq + 0][r] = v.x;
            As[kq + 1][r] = v.y;
            As[kq + 2][r] = v.z;
            As[kq + 3][r] = v.w;
        }
#pragma unroll
        for (int l = 0; l < 4; l++) {
            int i = t + l * 256;
            reinterpret_cast<float4*>(&Bs[0][0])[i] =
                reinterpret_cast<const float4*>(&W[(size_t)k0 * DIM])[i];
        }
        __syncthreads();

#pragma unroll
        for (int k = 0; k < 32; k++) {
            const unsigned long long* ap =
                reinterpret_cast<const unsigned long long*>(&As[k][tm * 8]);
            unsigned long long a2[4];
#pragma unroll
            for (int ii = 0; ii < 4; ii++) a2[ii] = ap[ii];

            float4 bv = *reinterpret_cast<const float4*>(&Bs[k][tn * 4]);
            unsigned long long bd[4];
            asm("mov.b64 %0, {%1, %1};" : "=l"(bd[0]) : "f"(bv.x));
            asm("mov.b64 %0, {%1, %1};" : "=l"(bd[1]) : "f"(bv.y));
            asm("mov.b64 %0, {%1, %1};" : "=l"(bd[2]) : "f"(bv.z));
            asm("mov.b64 %0, {%1, %1};" : "=l"(bd[3]) : "f"(bv.w));
#pragma unroll
            for (int ii = 0; ii < 4; ii++)
#pragma unroll
                for (int j = 0; j < 4; j++)
                    asm("fma.rn.f32x2 %0, %1, %2, %0;"
                        : "+l"(acc2[ii][j]) : "l"(a2[ii]), "l"(bd[j]));
        }
        __syncthreads();
    }

#pragma unroll
    for (int ii = 0; ii < 4; ii++) {
        float lo[4], hi[4];
#pragma unroll
        for (int j = 0; j < 4; j++)
            asm("mov.b64 {%0, %1}, %2;" : "=f"(lo[j]), "=f"(hi[j]) : "l"(acc2[ii][j]));
        int r0 = row0 + tm * 8 + 2 * ii;
        if (r0 < nrows) {
            __half2 p0 = __floats2half2_rn(lo[0], lo[1]);
            __half2 p1 = __floats2half2_rn(lo[2], lo[3]);
            uint2 u = make_uint2(*reinterpret_cast<unsigned*>(&p0),
                                 *reinterpret_cast<unsigned*>(&p1));
            *reinterpret_cast<uint2*>(&H[(size_t)r0 * DIM + tn * 4]) = u;
        }
        int r1 = r0 + 1;
        if (r1 < nrows) {
            __half2 p0 = __floats2half2_rn(hi[0], hi[1]);
            __half2 p1 = __floats2half2_rn(hi[2], hi[3]);
            uint2 u = make_uint2(*reinterpret_cast<unsigned*>(&p0),
                                 *reinterpret_cast<unsigned*>(&p1));
            *reinterpret_cast<uint2*>(&H[(size_t)r1 * DIM + tn * 4]) = u;
        }
    }
}

// ---------------------------------------------------------------------
// Warp-per-node gather; fp16 h rows, fp32 accumulation.
// ---------------------------------------------------------------------
__device__ __forceinline__ float4 gather_accum(const int* __restrict__ csr,
                                               const int* __restrict__ deg_s,
                                               int start, int cnt,
                                               const __half* __restrict__ h, int lane) {
    float4 acc = make_float4(0.f, 0.f, 0.f, 0.f);
    int j = 0;
    while (j < cnt) {
        int m = min(32, cnt - j);
        int idx = 0;
        float inv = 0.f;
        if (lane < m) {
            idx = __ldcs(&csr[start + j + lane]);
            inv = rsqrtf((float)deg_s[idx]);
        }
#pragma unroll 4
        for (int k = 0; k < m; k++) {
            int s = __shfl_sync(0xffffffffu, idx, k);
            float iv = __shfl_sync(0xffffffffu, inv, k);
            uint2 u = *reinterpret_cast<const uint2*>(&h[(size_t)s * DIM + lane * 4]);
            __half2 p0 = *reinterpret_cast<__half2*>(&u.x);
            __half2 p1 = *reinterpret_cast<__half2*>(&u.y);
            float2 f0 = __half22float2(p0);
            float2 f1 = __half22float2(p1);
            acc.x += f0.x * iv; acc.y += f0.y * iv;
            acc.z += f1.x * iv; acc.w += f1.y * iv;
        }
        j += m;
    }
    return acc;
}

// a-nodes: combine ba + aa
__global__ __launch_bounds__(256) void gather_a_kernel(float* __restrict__ out_a) {
    int gw = blockIdx.x * (blockDim.x >> 5) + (threadIdx.x >> 5);
    int lane = threadIdx.x & 31;
    if (gw >= NA) return;
    int d = gw;
    int c_ba = g_deg_t_ba[d];
    int c_aa = g_deg_t_aa[d];
    float4 s_ba = gather_accum(g_csr_ba, g_deg_s_ba, g_rs_ba[d], c_ba, g_h_ba, lane);
    float4 s_aa = gather_accum(g_csr_aa, g_deg_s_aa, g_rs_aa[d], c_aa, g_h_aa, lane);
    float rb = (c_ba > 0) ? rsqrtf((float)c_ba) * 0.5f : 0.f;
    float ra = (c_aa > 0) ? rsqrtf((float)c_aa) * 0.5f : 0.f;
    float4 v;
    v.x = fmaxf(s_ba.x * rb + s_aa.x * ra, 0.f);
    v.y = fmaxf(s_ba.y * rb + s_aa.y * ra, 0.f);
    v.z = fmaxf(s_ba.z * rb + s_aa.z * ra, 0.f);
    v.w = fmaxf(s_ba.w * rb + s_aa.w * ra, 0.f);
    __stcs(reinterpret_cast<float4*>(&out_a[(size_t)d * DIM + lane * 4]), v);
}

// b-nodes: ab only
__global__ __launch_bounds__(256) void gather_b_kernel(float* __restrict__ out_b) {
    int gw = blockIdx.x * (blockDim.x >> 5) + (threadIdx.x >> 5);
    int lane = threadIdx.x & 31;
    if (gw >= NB) return;
    int d = gw;
    int c_ab = g_deg_t_ab[d];
    float4 s_ab = gather_accum(g_csr_ab, g_deg_s_ab, g_rs_ab[d], c_ab, g_h_ab, lane);
    float r = (c_ab > 0) ? rsqrtf((float)c_ab) : 0.f;
    float4 v;
    v.x = fmaxf(s_ab.x * r, 0.f);
    v.y = fmaxf(s_ab.y * r, 0.f);
    v.z = fmaxf(s_ab.z * r, 0.f);
    v.w = fmaxf(s_ab.w * r, 0.f);
    __stcs(reinterpret_cast<float4*>(&out_b[(size_t)d * DIM + lane * 4]), v);
}

// ---------------------------------------------------------------------
extern "C" void kernel_launch(void* const* d_in, const int* in_sizes, int n_in,
                              void* d_out, int out_size) {
    const float* x_a  = (const float*)d_in[0];
    const float* x_b  = (const float*)d_in[1];
    const float* W_ab = (const float*)d_in[2];
    const float* W_ba = (const float*)d_in[3];
    const float* W_aa = (const float*)d_in[4];
    const int* src_ab = (const int*)d_in[5];
    const int* dst_ab = (const int*)d_in[6];
    const int* src_ba = (const int*)d_in[7];
    const int* dst_ba = (const int*)d_in[8];
    const int* src_aa = (const int*)d_in[9];
    const int* dst_aa = (const int*)d_in[10];

    float* out   = (float*)d_out;
    float* out_a = out;                       // [NA,128]
    float* out_b = out + (size_t)NA * DIM;    // [NB,128]

    __half *h_ab, *h_ba, *h_aa;
    cudaGetSymbolAddress((void**)&h_ab, g_h_ab);
    cudaGetSymbolAddress((void**)&h_ba, g_h_ba);
    cudaGetSymbolAddress((void**)&h_aa, g_h_aa);

    // ---- fork: side stream runs the 3 GEMMs (no degree dependency) ----
    cudaEventRecord(g_evFork, 0);
    cudaStreamWaitEvent(g_s1, g_evFork, 0);

    gemm128_kernel<<<(NB + 63) / 64, 256, 0, g_s1>>>(x_b, W_ba, h_ba, NB);
    gemm128_kernel<<<(NA + 63) / 64, 256, 0, g_s1>>>(x_a, W_aa, h_aa, NA);
    cudaEventRecord(g_evGemmA, g_s1);                    // h_ba + h_aa ready
    gemm128_kernel<<<(NA + 63) / 64, 256, 0, g_s1>>>(x_a, W_ab, h_ab, NA);

    // ---- main stream: CSR build ----
    zero_kernel<<<512, 256>>>();
    degree_kernel<<<(EE + 255) / 256, 256>>>(src_ab, dst_ab, src_ba, dst_ba, src_aa, dst_aa);
    scan3_kernel<<<3, 1024>>>();
    fill_kernel<<<(EE + 255) / 256, 256>>>(src_ab, dst_ab, src_ba, dst_ba, src_aa, dst_aa);
    cudaEventRecord(g_evCsr, 0);                         // CSR + degrees ready

    // gather_a on main stream: needs CSR (in-stream) + h_ba/h_aa (event)
    cudaStreamWaitEvent(0, g_evGemmA, 0);
    gather_a_kernel<<<(NA + 7) / 8, 256>>>(out_a);

    // gather_b on side stream: needs h_ab (in-stream) + CSR (event)
    cudaStreamWaitEvent(g_s1, g_evCsr, 0);
    gather_b_kernel<<<(NB + 7) / 8, 256, 0, g_s1>>>(out_b);
    cudaEventRecord(g_evTailB, g_s1);

    // join
    cudaStreamWaitEvent(0, g_evTailB, 0);
}